// round 1
// baseline (speedup 1.0000x reference)
#include <cuda_runtime.h>
#include <math.h>

// Problem constants
constexpr int C      = 1024;
constexpr int H      = 64;
constexpr int BM     = 128;     // rows per block
constexpr int XSTR   = 129;     // xs row stride (conflict-free: 8*129 % 32 != 0)
constexpr int BSTR   = 65;      // 64-wide buffer stride

// Shared memory layout (in floats)
constexpr int OFF_XS   = 0;                    // 128 x 129
constexpr int OFF_HTS  = OFF_XS  + BM * XSTR;  // 128 x 65 (raw ht)
constexpr int OFF_HS   = OFF_HTS + BM * BSTR;  // 128 x 65 (stage buf)
constexpr int OFF_MS   = OFF_HS  + BM * BSTR;  // 128 x 65 (m / h_next)
constexpr int OFF_WS   = OFF_MS  + BM * BSTR;  // 128 x 64 weights
constexpr int OFF_BN1  = OFF_WS  + 128 * 64;   // 128
constexpr int OFF_BN2  = OFF_BN1 + 128;        // 128
constexpr int OFF_BE   = OFF_BN2 + 128;        // 64
constexpr int OFF_BA   = OFF_BE  + 64;         // 64
constexpr int OFF_BIH  = OFF_BA  + 64;         // 192
constexpr int OFF_BHH  = OFF_BIH + 192;        // 192
constexpr int OFF_WP   = OFF_BHH + 192;        // 64
constexpr int OFF_ADJ  = OFF_WP  + 64;         // 256
constexpr int OFF_EA   = OFF_ADJ + 256;        // 128
constexpr int OFF_MASK = OFF_EA  + 128;        // 128
constexpr int OFF_SH1  = OFF_MASK+ 128;        // 64
constexpr int OFF_INT  = OFF_SH1 + 64;         // mrows(128 int) + mcount(1 int)
constexpr int SMEM_FLOATS = OFF_INT + 132;
constexpr int SMEM_BYTES  = SMEM_FLOATS * 4;

__device__ float g_adj[2 * C];

__device__ __forceinline__ float clip5f(float v) { return fminf(fmaxf(v, -5.f), 5.f); }
__device__ __forceinline__ float sigmf(float v) { return 1.f / (1.f + expf(-v)); }

// ---------------- adj precompute: adj[k][d] = clip(sum_c a0[c]*graphs[k,c,d]/denom) ----------
__global__ void adj_kernel(const int* __restrict__ qt,
                           const float* __restrict__ onehot,
                           const float* __restrict__ graphs) {
    __shared__ float a0s[C];
    __shared__ float denom_s;
    int d = threadIdx.x;
    int k = blockIdx.x;
    int qt0 = qt[0];
    a0s[d] = onehot[(size_t)qt0 * C + d];
    __syncthreads();
    if (d == 0) {
        float s = 0.f;
        for (int c = 0; c < C; ++c) s += a0s[c];
        denom_s = fmaxf(s, 1.f);
    }
    __syncthreads();
    float s = 0.f;
    for (int c = 0; c < C; ++c) {
        float a = a0s[c];
        if (a != 0.f) s = fmaf(a, graphs[((size_t)k * C + c) * C + d], s);
    }
    g_adj[k * C + d] = clip5f(s / denom_s);
}

// ---------------- GEMM tile helper: out = in(128 x KD) @ W(KD x 64) ------------------------
// 256 threads = 16 (rows of 8) x 16 (cols of 4). acc[8][4] per thread.
template <int KD>
__device__ __forceinline__ void gemm_tile(const float* __restrict__ inS, int inStride, int inOff,
                                          const float* __restrict__ ws,
                                          float acc[8][4], int tm, int tn) {
    const float* xb = inS + tm * 8 * inStride + inOff;
    const float* wb = ws + tn * 4;
#pragma unroll 4
    for (int i = 0; i < KD; ++i) {
        float4 wv = *(const float4*)(wb + i * 64);
#pragma unroll
        for (int rr = 0; rr < 8; ++rr) {
            float xv = xb[rr * inStride + i];
            acc[rr][0] = fmaf(xv, wv.x, acc[rr][0]);
            acc[rr][1] = fmaf(xv, wv.y, acc[rr][1]);
            acc[rr][2] = fmaf(xv, wv.z, acc[rr][2]);
            acc[rr][3] = fmaf(xv, wv.w, acc[rr][3]);
        }
    }
}

__device__ __forceinline__ void load_w64(float* __restrict__ ws, const float* __restrict__ src,
                                         int rows, int srcStride, int srcOff) {
    int n4 = rows * 16;
    for (int e = threadIdx.x; e < n4; e += 256) {
        int i = e >> 4, j4 = e & 15;
        *(float4*)(ws + i * 64 + j4 * 4) =
            *(const float4*)(src + (size_t)i * srcStride + srcOff + j4 * 4);
    }
}

// ---------------- main fused kernel ------------------------------------------------------
__global__ void __launch_bounds__(256, 1)
fused_kernel(const int* __restrict__ qt, const float* __restrict__ ht,
             const float* __restrict__ onehot, const float* __restrict__ kc,
             const float* __restrict__ nwp,
             const float* __restrict__ Ws1, const float* __restrict__ bs1,
             const float* __restrict__ Ws2, const float* __restrict__ bs2,
             const float* __restrict__ Wn1, const float* __restrict__ bn1,
             const float* __restrict__ Wn2, const float* __restrict__ bn2,
             const float* __restrict__ ea, const float* __restrict__ We,
             const float* __restrict__ be, const float* __restrict__ Wa,
             const float* __restrict__ ba, const float* __restrict__ Wih,
             const float* __restrict__ bih, const float* __restrict__ Whh,
             const float* __restrict__ bhh, const float* __restrict__ Wp,
             const float* __restrict__ bp, float* __restrict__ out) {
    extern __shared__ float sm[];
    float* xs   = sm + OFF_XS;
    float* hts  = sm + OFF_HTS;
    float* hs   = sm + OFF_HS;
    float* ms   = sm + OFF_MS;
    float* ws   = sm + OFF_WS;
    float* bn1s = sm + OFF_BN1;
    float* bn2s = sm + OFF_BN2;
    float* bes  = sm + OFF_BE;
    float* bas  = sm + OFF_BA;
    float* bihs = sm + OFF_BIH;
    float* bhhs = sm + OFF_BHH;
    float* Wps  = sm + OFF_WP;
    float* adjs = sm + OFF_ADJ;
    float* eas  = sm + OFF_EA;
    float* masks= sm + OFF_MASK;
    float* sh1  = sm + OFF_SH1;
    int*   mrows  = (int*)(sm + OFF_INT);
    int*   mcount = mrows + 128;

    const int tid = threadIdx.x;
    const int tm  = tid >> 4;    // 0..15, 8 rows each
    const int tn  = tid & 15;    // 0..15, 4 cols each
    const int r0  = blockIdx.x * BM;          // global row = b*C + c
    const int b   = r0 >> 10;
    const int c0  = r0 & (C - 1);

    const float nw = fminf(fmaxf(nwp[0], 0.1f), 0.9f);
    const int qtb  = qt[b];

    if (tid == 0) *mcount = 0;

    // ---- load ht tile (raw -> hts, clipped -> xs[:, 0:64]) ----
    const float* htp = ht + (size_t)r0 * H;
    for (int e = tid; e < BM * 16; e += 256) {
        float4 v = *(const float4*)(htp + e * 4);
        int r = e >> 4, h4 = (e & 15) * 4;
        hts[r * BSTR + h4 + 0] = v.x;  hts[r * BSTR + h4 + 1] = v.y;
        hts[r * BSTR + h4 + 2] = v.z;  hts[r * BSTR + h4 + 3] = v.w;
        xs[r * XSTR + h4 + 0] = clip5f(v.x);  xs[r * XSTR + h4 + 1] = clip5f(v.y);
        xs[r * XSTR + h4 + 2] = clip5f(v.z);  xs[r * XSTR + h4 + 3] = clip5f(v.w);
    }
    // ---- kc tile -> xs[:, 64:128] (clip is a no-op for kc but applied for exactness) ----
    const float* kcp = kc + (size_t)c0 * H;
    for (int e = tid; e < BM * 16; e += 256) {
        float4 v = *(const float4*)(kcp + e * 4);
        int r = e >> 4, h4 = 64 + (e & 15) * 4;
        xs[r * XSTR + h4 + 0] = clip5f(v.x);  xs[r * XSTR + h4 + 1] = clip5f(v.y);
        xs[r * XSTR + h4 + 2] = clip5f(v.z);  xs[r * XSTR + h4 + 3] = clip5f(v.w);
    }
    // ---- small arrays ----
    if (tid < 64) {
        bn1s[tid] = bn1[tid];      bn1s[64 + tid] = bn1[64 + tid];
        bn2s[tid] = bn2[tid];      bn2s[64 + tid] = bn2[64 + tid];
        bes[tid]  = be[tid];       bas[tid]  = ba[tid];
        Wps[tid]  = Wp[tid];
    }
    if (tid < 192) { bihs[tid] = bih[tid];  bhhs[tid] = bhh[tid]; }
    if (tid < 128) {
        adjs[tid]       = g_adj[c0 + tid];
        adjs[128 + tid] = g_adj[C + c0 + tid];
        eas[tid]        = ea[c0 + tid];
        masks[tid]      = onehot[(size_t)qtb * C + c0 + tid];
    }
    __syncthreads();

    if (tid < 128 && masks[tid] > 0.5f) {
        int p = atomicAdd(mcount, 1);
        mrows[p] = tid;
    }

    // ---- neighbor MLPs (mask=0 path: only second half of Wn1 matters) ----
    for (int k = 0; k < 2; ++k) {
        __syncthreads();
        load_w64(ws, Wn1 + (size_t)(k * 256 + 128) * 64, 128, 64, 0);
        __syncthreads();
        {
            float acc[8][4];
#pragma unroll
            for (int rr = 0; rr < 8; ++rr)
#pragma unroll
                for (int cc = 0; cc < 4; ++cc) acc[rr][cc] = bn1s[k * 64 + tn * 4 + cc];
            gemm_tile<128>(xs, XSTR, 0, ws, acc, tm, tn);
#pragma unroll
            for (int rr = 0; rr < 8; ++rr)
#pragma unroll
                for (int cc = 0; cc < 4; ++cc)
                    hs[(tm * 8 + rr) * BSTR + tn * 4 + cc] = fmaxf(acc[rr][cc], 0.f);
        }
        __syncthreads();
        load_w64(ws, Wn2 + (size_t)k * 64 * 64, 64, 64, 0);
        __syncthreads();
        {
            float acc[8][4];
#pragma unroll
            for (int rr = 0; rr < 8; ++rr)
#pragma unroll
                for (int cc = 0; cc < 4; ++cc) acc[rr][cc] = bn2s[k * 64 + tn * 4 + cc];
            gemm_tile<64>(hs, BSTR, 0, ws, acc, tm, tn);
#pragma unroll
            for (int rr = 0; rr < 8; ++rr) {
                int row = tm * 8 + rr;
#pragma unroll
                for (int cc = 0; cc < 4; ++cc) {
                    float nb = fminf(fmaxf(acc[rr][cc], 0.f), 5.f);  // relu then clip
                    float* mp = &ms[row * BSTR + tn * 4 + cc];
                    if (k == 0) *mp = clip5f(adjs[row] * nb);
                    else        *mp = clip5f(nw * (*mp) + (1.f - nw) * adjs[128 + row] * nb);
                }
            }
        }
    }
    __syncthreads();

    // ---- self path for masked rows (rare): overwrite ms[row] with self_feat ----
    int mc = *mcount;
    for (int mi = 0; mi < mc; ++mi) {
        int r = mrows[mi];
        if (tid < 64) {
            float s = bs1[tid];
            for (int i = 0; i < 64; ++i) s = fmaf(hts[r * BSTR + i], Ws1[i * 64 + tid], s);
            for (int i = 0; i < 64; ++i) s = fmaf(xs[r * XSTR + 64 + i], Ws1[(64 + i) * 64 + tid], s);
            sh1[tid] = fmaxf(s, 0.f);
        }
        __syncthreads();
        if (tid < 64) {
            float s = bs2[tid];
            for (int i = 0; i < 64; ++i) s = fmaf(sh1[i], Ws2[i * 64 + tid], s);
            ms[r * BSTR + tid] = fminf(fmaxf(s, 0.f), 10.f);  // relu then clip(-10,10)
        }
        __syncthreads();
    }

    // ---- res = m - g*sigmoid(m@We+be)*m + g*tanh(m@Wa+ba); also pack [res|ht] into xs ----
    __syncthreads();
    load_w64(ws, We, 64, 64, 0);
    load_w64(ws + 4096, Wa, 64, 64, 0);
    __syncthreads();
    {
        float au[8][4], av[8][4];
#pragma unroll
        for (int rr = 0; rr < 8; ++rr)
#pragma unroll
            for (int cc = 0; cc < 4; ++cc) { au[rr][cc] = bes[tn * 4 + cc]; av[rr][cc] = bas[tn * 4 + cc]; }
        gemm_tile<64>(ms, BSTR, 0, ws, au, tm, tn);
        gemm_tile<64>(ms, BSTR, 0, ws + 4096, av, tm, tn);
#pragma unroll
        for (int rr = 0; rr < 8; ++rr) {
            int row = tm * 8 + rr;
            float g = eas[row];
#pragma unroll
            for (int cc = 0; cc < 4; ++cc) {
                int j = tn * 4 + cc;
                float m = ms[row * BSTR + j];
                float res = m - g * sigmf(au[rr][cc]) * m + g * tanhf(av[rr][cc]);
                xs[row * XSTR + j]      = res;
                xs[row * XSTR + 64 + j] = hts[row * BSTR + j];  // raw ht for GRU
            }
        }
    }

    // ---- GRU gate r: sigmoid([res|ht] @ [Wih_r; Whh_r] + b) -> ms ----
    __syncthreads();
    load_w64(ws, Wih, 64, 192, 0);
    load_w64(ws + 4096, Whh, 64, 192, 0);
    __syncthreads();
    {
        float acc[8][4];
#pragma unroll
        for (int rr = 0; rr < 8; ++rr)
#pragma unroll
            for (int cc = 0; cc < 4; ++cc) acc[rr][cc] = bihs[tn * 4 + cc] + bhhs[tn * 4 + cc];
        gemm_tile<128>(xs, XSTR, 0, ws, acc, tm, tn);
#pragma unroll
        for (int rr = 0; rr < 8; ++rr)
#pragma unroll
            for (int cc = 0; cc < 4; ++cc)
                ms[(tm * 8 + rr) * BSTR + tn * 4 + cc] = sigmf(acc[rr][cc]);
    }

    // ---- GRU gate z -> hs ----
    __syncthreads();
    load_w64(ws, Wih, 64, 192, 64);
    load_w64(ws + 4096, Whh, 64, 192, 64);
    __syncthreads();
    {
        float acc[8][4];
#pragma unroll
        for (int rr = 0; rr < 8; ++rr)
#pragma unroll
            for (int cc = 0; cc < 4; ++cc)
                acc[rr][cc] = bihs[64 + tn * 4 + cc] + bhhs[64 + tn * 4 + cc];
        gemm_tile<128>(xs, XSTR, 0, ws, acc, tm, tn);
#pragma unroll
        for (int rr = 0; rr < 8; ++rr)
#pragma unroll
            for (int cc = 0; cc < 4; ++cc)
                hs[(tm * 8 + rr) * BSTR + tn * 4 + cc] = sigmf(acc[rr][cc]);
    }

    // ---- in_ = res @ Wih_n + b -> hts ----
    __syncthreads();
    load_w64(ws, Wih, 64, 192, 128);
    __syncthreads();
    {
        float acc[8][4];
#pragma unroll
        for (int rr = 0; rr < 8; ++rr)
#pragma unroll
            for (int cc = 0; cc < 4; ++cc) acc[rr][cc] = bihs[128 + tn * 4 + cc];
        gemm_tile<64>(xs, XSTR, 0, ws, acc, tm, tn);
#pragma unroll
        for (int rr = 0; rr < 8; ++rr)
#pragma unroll
            for (int cc = 0; cc < 4; ++cc)
                hts[(tm * 8 + rr) * BSTR + tn * 4 + cc] = acc[rr][cc];
    }

    // ---- hn = ht @ Whh_n + b; fuse n, h_next; write h_next -> ms ----
    __syncthreads();
    load_w64(ws, Whh, 64, 192, 128);
    __syncthreads();
    {
        float acc[8][4];
#pragma unroll
        for (int rr = 0; rr < 8; ++rr)
#pragma unroll
            for (int cc = 0; cc < 4; ++cc) acc[rr][cc] = bhhs[128 + tn * 4 + cc];
        gemm_tile<64>(xs, XSTR, 64, ws, acc, tm, tn);
#pragma unroll
        for (int rr = 0; rr < 8; ++rr) {
            int row = tm * 8 + rr;
#pragma unroll
            for (int cc = 0; cc < 4; ++cc) {
                int j = tn * 4 + cc;
                float hn  = acc[rr][cc];
                float r_  = ms[row * BSTR + j];
                float z_  = hs[row * BSTR + j];
                float in_ = hts[row * BSTR + j];
                float n_  = tanhf(in_ + r_ * hn);
                float hp  = xs[row * XSTR + 64 + j];
                ms[row * BSTR + j] = (1.f - z_) * n_ + z_ * hp;
            }
        }
    }
    __syncthreads();

    // ---- y = sigmoid(h_next @ Wp + bp) ----
    if (tid < 128) {
        float s = bp[0];
#pragma unroll
        for (int j = 0; j < 64; ++j) s = fmaf(ms[tid * BSTR + j], Wps[j], s);
        out[r0 + tid] = sigmf(s);
    }
}

// ---------------- launch -----------------------------------------------------------------
extern "C" void kernel_launch(void* const* d_in, const int* in_sizes, int n_in,
                              void* d_out, int out_size) {
    const int*   qt     = (const int*)d_in[1];
    const float* ht     = (const float*)d_in[2];
    const float* onehot = (const float*)d_in[3];
    const float* kc     = (const float*)d_in[4];
    const float* graphs = (const float*)d_in[5];
    const float* nw     = (const float*)d_in[6];
    const float* Ws1    = (const float*)d_in[7];
    const float* bs1    = (const float*)d_in[8];
    const float* Ws2    = (const float*)d_in[9];
    const float* bs2    = (const float*)d_in[10];
    const float* Wn1    = (const float*)d_in[11];
    const float* bn1    = (const float*)d_in[12];
    const float* Wn2    = (const float*)d_in[13];
    const float* bn2    = (const float*)d_in[14];
    const float* ea     = (const float*)d_in[15];
    const float* We     = (const float*)d_in[16];
    const float* be     = (const float*)d_in[17];
    const float* Wa     = (const float*)d_in[18];
    const float* ba     = (const float*)d_in[19];
    const float* Wih    = (const float*)d_in[20];
    const float* bih    = (const float*)d_in[21];
    const float* Whh    = (const float*)d_in[22];
    const float* bhh    = (const float*)d_in[23];
    const float* Wp     = (const float*)d_in[24];
    const float* bp     = (const float*)d_in[25];
    float* out = (float*)d_out;

    cudaFuncSetAttribute(fused_kernel, cudaFuncAttributeMaxDynamicSharedMemorySize, SMEM_BYTES);

    adj_kernel<<<2, 1024>>>(qt, onehot, graphs);
    fused_kernel<<<(256 * 1024) / BM, 256, SMEM_BYTES>>>(
        qt, ht, onehot, kc, nw, Ws1, bs1, Ws2, bs2, Wn1, bn1, Wn2, bn2,
        ea, We, be, Wa, ba, Wih, bih, Whh, bhh, Wp, bp, out);
}